// round 5
// baseline (speedup 1.0000x reference)
#include <cuda_runtime.h>
typedef unsigned long long u64;
#define NB 16
#define NH 8

__device__ float g_m[NB * NH * 1024];        // tanh-MLP, [b][h][n]
__device__ float g_A[NB * NH * 4 * 128];     // per (b,h,chunk): A+[64], A-[64]

__device__ __forceinline__ u64 pack2(float a, float b) {
    u64 r; asm("mov.b64 %0,{%1,%2};" : "=l"(r) : "f"(a), "f"(b)); return r;
}
__device__ __forceinline__ void fma2(u64& d, u64 a, u64 b) {
    asm("fma.rn.f32x2 %0,%1,%2,%0;" : "+l"(d) : "l"(a), "l"(b));
}
__device__ __forceinline__ float2 unpack2(u64 v) {
    float2 r; asm("mov.b64 {%0,%1},%2;" : "=f"(r.x), "=f"(r.y) : "l"(v)); return r;
}
__device__ __forceinline__ unsigned su32(const void* p) {
    unsigned r;
    asm("{.reg .u64 t; cvta.to.shared.u64 t,%1; cvt.u32.u64 %0,t;}" : "=r"(r) : "l"(p));
    return r;
}
#define CP16(d, s) asm volatile("cp.async.cg.shared.global [%0],[%1],16;" :: "r"(d), "l"(s))
#define CPC()      asm volatile("cp.async.commit_group;")

// ---------- k1: MLP m = tanh(x@W^T + b); thread = (row, h) ----------
__global__ void __launch_bounds__(256) k1_mlp(const float* __restrict__ x,
                                              const float* __restrict__ w,
                                              const float* __restrict__ bias) {
    __shared__ __align__(16) float sw[8 * 1024];
    __shared__ float sb[8];
    int tid = threadIdx.x;
    for (int i = tid; i < 2048; i += 256)
        ((float4*)sw)[i] = ((const float4*)w)[i];
    if (tid < 8) sb[tid] = bias[tid];
    __syncthreads();

    int gid = blockIdx.x * 256 + tid;
    int row = gid >> 3, h = gid & 7;
    const ulonglong2* xr = (const ulonglong2*)(x + (long)row * 1024);
    const ulonglong2* wr = (const ulonglong2*)(sw + h * 1024);
    u64 acc0 = 0ull, acc1 = 0ull;
#pragma unroll 8
    for (int j = 0; j < 256; ++j) {
        ulonglong2 xv = xr[j];
        ulonglong2 wv = wr[j];
        fma2(acc0, xv.x, wv.x);
        fma2(acc1, xv.y, wv.y);
    }
    float2 a = unpack2(acc0), c = unpack2(acc1);
    float v = tanhf(a.x + a.y + c.x + c.y + sb[h]);
    int b = row >> 10, j = row & 1023;
    g_m[(b * 8 + (j >> 7)) * 1024 + ((j & 127) << 3) + h] = v;
}

// ---------- k2: partial A+/-[e] over 256-n chunks ----------
__global__ void __launch_bounds__(256) k2_A(const float* __restrict__ Q) {
    int chunk = blockIdx.x, h = blockIdx.y, b = blockIdx.z;
    int tid = threadIdx.x;
    int e = tid & 63, st = tid >> 6;
    int n0 = chunk * 256 + st * 64;
    const float* mp = g_m + (b * 8 + h) * 1024 + n0;
    const float* qp = Q + ((long)(b * 1024 + n0) * 8 + h) * 64 + e;
    float ap = 0.f, an = 0.f;
#pragma unroll 8
    for (int n = 0; n < 64; ++n) {
        float m = mp[n];
        float qv = qp[(long)n * 512];
        ap += fmaxf(m, 0.f) * qv;
        an += fminf(m, 0.f) * qv;
    }
    __shared__ float sp[4][64], sn[4][64];
    sp[st][e] = ap; sn[st][e] = an;
    __syncthreads();
    long base = ((long)(b * 8 + h) * 4 + chunk) * 128;
    if (tid < 64)
        g_A[base + tid] = sp[0][tid] + sp[1][tid] + sp[2][tid] + sp[3][tid];
    else if (tid < 128) {
        int e2 = tid & 63;
        g_A[base + 64 + e2] = sn[0][e2] + sn[1][e2] + sn[2][e2] + sn[3][e2];
    }
}

// ---------- k3: u,t = K·A+-, rank-2 softmax, out[e,g] = sum_s V[s,e] P[s,g] ----------
__global__ void __launch_bounds__(256, 1) k3_attn(const float* __restrict__ K,
                                                  const float* __restrict__ V,
                                                  const float* __restrict__ sW,
                                                  float* __restrict__ out) {
    __shared__ __align__(16) float SM[10880];
    __shared__ float sA[128];
    float* sP = SM + 8704;
    const int h = blockIdx.x, b = blockIdx.y, tid = threadIdx.x;
    const unsigned smb = su32(SM);
    const int part = tid & 7, sl = tid >> 3;
    const int quarter = tid >> 6, eg = (tid >> 3) & 7, gg = tid & 7;

    if (tid < 128) {
        const float* Ab = g_A + (long)(b * 8 + h) * 512 + tid;
        sA[tid] = Ab[0] + Ab[128] + Ab[256] + Ab[384];
    }

    const float* Kb = K + ((long)b * 8192 + h) * 64;
    const float* Vb = V + ((long)b * 8192 + h) * 64;

    // prologue: stage tile 0 into buffer 0
#pragma unroll
    for (int i = 0; i < 2; ++i) {
        int idx = i * 256 + tid;
        int row = idx >> 4, col = (idx & 15) << 2;
        long go = (long)row * 512 + col;
        unsigned so = ((unsigned)(row * 68 + col)) << 2;
        CP16(smb + so, Kb + go);
        CP16(smb + 4352 * 4 + so, Vb + go);
    }
    CPC();

    float ra[8], rc[8];
#pragma unroll
    for (int j = 0; j < 8; ++j) {
        float w = sW[h * 64 + part * 8 + j];
        ra[j] = 0.125f * fmaxf(w, 0.f);
        rc[j] = 0.125f * fminf(w, 0.f);
    }
    __syncthreads();
    float rAp[8], rAn[8];
#pragma unroll
    for (int i = 0; i < 8; ++i) { rAp[i] = sA[part * 8 + i]; rAn[i] = sA[64 + part * 8 + i]; }

    u64 acc[32];
#pragma unroll
    for (int i = 0; i < 32; ++i) acc[i] = 0ull;

    for (int t = 0; t < 32; ++t) {
        int buf = t & 1;
        if (t + 1 < 32) {
            int s0 = (t + 1) * 32, nb = buf ^ 1;
#pragma unroll
            for (int i = 0; i < 2; ++i) {
                int idx = i * 256 + tid;
                int row = idx >> 4, col = (idx & 15) << 2;
                long go = (long)(s0 + row) * 512 + col;
                unsigned so = ((unsigned)(nb * 2176 + row * 68 + col)) << 2;
                CP16(smb + so, Kb + go);
                CP16(smb + 4352 * 4 + so, Vb + go);
            }
            CPC();
            asm volatile("cp.async.wait_group 1;");
        } else {
            asm volatile("cp.async.wait_group 0;");
        }
        __syncthreads();

        // u,t for s = sl (8 lanes each cover 8 e)
        const float* kr = SM + buf * 2176 + sl * 68 + part * 8;
        float u = 0.f, tt = 0.f;
#pragma unroll
        for (int i = 0; i < 8; ++i) { float kv = kr[i]; u += kv * rAp[i]; tt += kv * rAn[i]; }
#pragma unroll
        for (int off = 1; off < 8; off <<= 1) {
            u  += __shfl_xor_sync(0xffffffffu, u,  off);
            tt += __shfl_xor_sync(0xffffffffu, tt, off);
        }
        // softmax slice: 8 g per thread
        float l[8], mx = -1e30f;
#pragma unroll
        for (int j = 0; j < 8; ++j) { l[j] = u * ra[j] + tt * rc[j]; mx = fmaxf(mx, l[j]); }
#pragma unroll
        for (int off = 1; off < 8; off <<= 1)
            mx = fmaxf(mx, __shfl_xor_sync(0xffffffffu, mx, off));
        float sum = 0.f;
#pragma unroll
        for (int j = 0; j < 8; ++j) { l[j] = __expf(l[j] - mx); sum += l[j]; }
#pragma unroll
        for (int off = 1; off < 8; off <<= 1)
            sum += __shfl_xor_sync(0xffffffffu, sum, off);
        float inv = __fdividef(1.f, sum);
        *(float4*)&sP[sl * 68 + part * 8]     = make_float4(l[0] * inv, l[1] * inv, l[2] * inv, l[3] * inv);
        *(float4*)&sP[sl * 68 + part * 8 + 4] = make_float4(l[4] * inv, l[5] * inv, l[6] * inv, l[7] * inv);
        __syncthreads();

        // phase B: each quarter covers full 64x64 over its 8 s
        const float* vb = SM + 4352 + buf * 2176;
#pragma unroll
        for (int s8 = 0; s8 < 8; ++s8) {
            int sq = quarter * 8 + s8;
            float4 v0 = *(const float4*)&vb[sq * 68 + eg * 8];
            float4 v1 = *(const float4*)&vb[sq * 68 + eg * 8 + 4];
            ulonglong2 pA = *(const ulonglong2*)&sP[sq * 68 + gg * 8];
            ulonglong2 pB = *(const ulonglong2*)&sP[sq * 68 + gg * 8 + 4];
            float ve[8] = {v0.x, v0.y, v0.z, v0.w, v1.x, v1.y, v1.z, v1.w};
#pragma unroll
            for (int e = 0; e < 8; ++e) {
                u64 vv = pack2(ve[e], ve[e]);
                fma2(acc[e * 4 + 0], vv, pA.x);
                fma2(acc[e * 4 + 1], vv, pA.y);
                fma2(acc[e * 4 + 2], vv, pB.x);
                fma2(acc[e * 4 + 3], vv, pB.y);
            }
        }
        __syncthreads();
    }

    // reduce the 4 quarter-copies (reuse sK/sV region as u64 buffer)
    u64* sred = (u64*)SM;
    if (tid >= 128) {
        int j = tid - 128;
#pragma unroll
        for (int i = 0; i < 32; ++i) sred[j * 32 + i] = acc[i];
    }
    __syncthreads();
    if (tid < 128) {
#pragma unroll
        for (int i = 0; i < 32; ++i) {
            float2 a = unpack2(acc[i]), c = unpack2(sred[tid * 32 + i]);
            acc[i] = pack2(a.x + c.x, a.y + c.y);
        }
    }
    __syncthreads();
    if (tid >= 64 && tid < 128) {
#pragma unroll
        for (int i = 0; i < 32; ++i) sred[(tid - 64) * 32 + i] = acc[i];
    }
    __syncthreads();
    if (tid < 64) {
#pragma unroll
        for (int i = 0; i < 32; ++i) {
            float2 a = unpack2(acc[i]), c = unpack2(sred[tid * 32 + i]);
            acc[i] = pack2(a.x + c.x, a.y + c.y);
        }
#pragma unroll
        for (int e = 0; e < 8; ++e) {
            long ob = ((long)(b * 64 + eg * 8 + e) * 8 + h) * 64 + gg * 8;
            float2 p0 = unpack2(acc[e * 4 + 0]), p1 = unpack2(acc[e * 4 + 1]);
            float2 p2 = unpack2(acc[e * 4 + 2]), p3 = unpack2(acc[e * 4 + 3]);
            *(float4*)&out[ob]     = make_float4(p0.x, p0.y, p1.x, p1.y);
            *(float4*)&out[ob + 4] = make_float4(p2.x, p2.y, p3.x, p3.y);
        }
    }
}

extern "C" void kernel_launch(void* const* d_in, const int* in_sizes, int n_in,
                              void* d_out, int out_size) {
    const float* q  = (const float*)d_in[0];
    const float* k  = (const float*)d_in[1];
    const float* v  = (const float*)d_in[2];
    const float* x  = (const float*)d_in[3];
    const float* mw = (const float*)d_in[4];
    const float* mb = (const float*)d_in[5];
    const float* sW = (const float*)d_in[6];
    (void)in_sizes; (void)n_in; (void)out_size;
    float* out = (float*)d_out;

    k1_mlp<<<512, 256>>>(x, mw, mb);
    k2_A<<<dim3(4, NH, NB), 256>>>(q);
    k3_attn<<<dim3(NH, NB), 256>>>(k, v, sW, out);
}

// round 6
// speedup vs baseline: 2.4232x; 2.4232x over previous
#include <cuda_runtime.h>
typedef unsigned long long u64;
#define NB 16
#define NH 8

__device__ float g_m[NB * NH * 1024];        // tanh-MLP, [b][h][n]
__device__ float g_A[NB * NH * 4 * 128];     // per (b,h,chunk): A+[64], A-[64]

__device__ __forceinline__ u64 pack2(float a, float b) {
    u64 r; asm("mov.b64 %0,{%1,%2};" : "=l"(r) : "f"(a), "f"(b)); return r;
}
__device__ __forceinline__ void fma2(u64& d, u64 a, u64 b) {
    asm("fma.rn.f32x2 %0,%1,%2,%0;" : "+l"(d) : "l"(a), "l"(b));
}
__device__ __forceinline__ float2 unpack2(u64 v) {
    float2 r; asm("mov.b64 {%0,%1},%2;" : "=f"(r.x), "=f"(r.y) : "l"(v)); return r;
}
__device__ __forceinline__ unsigned su32(const void* p) {
    unsigned r;
    asm("{.reg .u64 t; cvta.to.shared.u64 t,%1; cvt.u32.u64 %0,t;}" : "=r"(r) : "l"(p));
    return r;
}
#define CP16(d, s) asm volatile("cp.async.cg.shared.global [%0],[%1],16;" :: "r"(d), "l"(s))
#define CPC()      asm volatile("cp.async.commit_group;")

// ---------- k1: MLP m = tanh(x@W^T + b); warp = 4 rows x 8 heads ----------
__global__ void __launch_bounds__(256) k1_mlp(const float* __restrict__ x,
                                              const float* __restrict__ w,
                                              const float* __restrict__ bias) {
    __shared__ __align__(16) float sw[8 * 1024];
    __shared__ float sb[8];
    int tid = threadIdx.x;
    for (int i = tid; i < 2048; i += 256)
        ((float4*)sw)[i] = ((const float4*)w)[i];
    if (tid < 8) sb[tid] = bias[tid];
    __syncthreads();

    int warp = tid >> 5, lane = tid & 31;
    int row0 = blockIdx.x * 32 + warp * 4;
    const float4* x0 = (const float4*)(x + (long)row0 * 1024);

    float acc[4][8];
#pragma unroll
    for (int r = 0; r < 4; ++r)
#pragma unroll
        for (int h = 0; h < 8; ++h) acc[r][h] = 0.f;

    for (int j = 0; j < 8; ++j) {
        float4 xv[4];
#pragma unroll
        for (int r = 0; r < 4; ++r) xv[r] = x0[r * 256 + j * 32 + lane];
#pragma unroll
        for (int h = 0; h < 8; ++h) {
            float4 wv = *(const float4*)&sw[h * 1024 + lane * 4 + j * 128];
#pragma unroll
            for (int r = 0; r < 4; ++r)
                acc[r][h] += xv[r].x * wv.x + xv[r].y * wv.y +
                             xv[r].z * wv.z + xv[r].w * wv.w;
        }
    }

    // butterfly reduce all 32 (r,h) sums across the warp
#pragma unroll
    for (int r = 0; r < 4; ++r)
#pragma unroll
        for (int h = 0; h < 8; ++h)
#pragma unroll
            for (int off = 16; off > 0; off >>= 1)
                acc[r][h] += __shfl_xor_sync(0xffffffffu, acc[r][h], off);

    // lane owns (r = lane>>3, h = lane&7); predicated select (no dyn index)
    float sel = 0.f;
#pragma unroll
    for (int r = 0; r < 4; ++r)
#pragma unroll
        for (int h = 0; h < 8; ++h)
            if (lane == r * 8 + h) sel = acc[r][h];

    int hh = lane & 7;
    int row = row0 + (lane >> 3);
    float v = tanhf(sel + sb[hh]);
    int b = row >> 10, j = row & 1023;
    g_m[(b * 8 + (j >> 7)) * 1024 + ((j & 127) << 3) + hh] = v;
}

// ---------- k2: partial A+/-[e] over 256-n chunks ----------
__global__ void __launch_bounds__(256) k2_A(const float* __restrict__ Q) {
    int chunk = blockIdx.x, h = blockIdx.y, b = blockIdx.z;
    int tid = threadIdx.x;
    int e = tid & 63, st = tid >> 6;
    int n0 = chunk * 256 + st * 64;
    const float* mp = g_m + (b * 8 + h) * 1024 + n0;
    const float* qp = Q + ((long)(b * 1024 + n0) * 8 + h) * 64 + e;
    float ap = 0.f, an = 0.f;
#pragma unroll 8
    for (int n = 0; n < 64; ++n) {
        float m = mp[n];
        float qv = qp[(long)n * 512];
        ap += fmaxf(m, 0.f) * qv;
        an += fminf(m, 0.f) * qv;
    }
    __shared__ float sp[4][64], sn[4][64];
    sp[st][e] = ap; sn[st][e] = an;
    __syncthreads();
    long base = ((long)(b * 8 + h) * 4 + chunk) * 128;
    if (tid < 64)
        g_A[base + tid] = sp[0][tid] + sp[1][tid] + sp[2][tid] + sp[3][tid];
    else if (tid < 128) {
        int e2 = tid & 63;
        g_A[base + 64 + e2] = sn[0][e2] + sn[1][e2] + sn[2][e2] + sn[3][e2];
    }
}

// ---------- k3: u,t = K·A+-, rank-2 softmax, out[e,g] = sum_s V[s,e] P[s,g] ----------
__global__ void __launch_bounds__(256, 1) k3_attn(const float* __restrict__ K,
                                                  const float* __restrict__ V,
                                                  const float* __restrict__ sW,
                                                  float* __restrict__ out) {
    __shared__ __align__(16) float SM[10880];
    __shared__ float sA[128];
    float* sP = SM + 8704;
    const int h = blockIdx.x, b = blockIdx.y, tid = threadIdx.x;
    const unsigned smb = su32(SM);
    const int part = tid & 7, sl = tid >> 3;
    const int quarter = tid >> 6, eg = (tid >> 3) & 7, gg = tid & 7;

    if (tid < 128) {
        const float* Ab = g_A + (long)(b * 8 + h) * 512 + tid;
        sA[tid] = Ab[0] + Ab[128] + Ab[256] + Ab[384];
    }

    const float* Kb = K + ((long)b * 8192 + h) * 64;
    const float* Vb = V + ((long)b * 8192 + h) * 64;

#pragma unroll
    for (int i = 0; i < 2; ++i) {
        int idx = i * 256 + tid;
        int row = idx >> 4, col = (idx & 15) << 2;
        long go = (long)row * 512 + col;
        unsigned so = ((unsigned)(row * 68 + col)) << 2;
        CP16(smb + so, Kb + go);
        CP16(smb + 4352 * 4 + so, Vb + go);
    }
    CPC();

    float ra[8], rc[8];
#pragma unroll
    for (int j = 0; j < 8; ++j) {
        float w = sW[h * 64 + part * 8 + j];
        ra[j] = 0.125f * fmaxf(w, 0.f);
        rc[j] = 0.125f * fminf(w, 0.f);
    }
    __syncthreads();
    float rAp[8], rAn[8];
#pragma unroll
    for (int i = 0; i < 8; ++i) { rAp[i] = sA[part * 8 + i]; rAn[i] = sA[64 + part * 8 + i]; }

    u64 acc[32];
#pragma unroll
    for (int i = 0; i < 32; ++i) acc[i] = 0ull;

    for (int t = 0; t < 32; ++t) {
        int buf = t & 1;
        if (t + 1 < 32) {
            int s0 = (t + 1) * 32, nb = buf ^ 1;
#pragma unroll
            for (int i = 0; i < 2; ++i) {
                int idx = i * 256 + tid;
                int row = idx >> 4, col = (idx & 15) << 2;
                long go = (long)(s0 + row) * 512 + col;
                unsigned so = ((unsigned)(nb * 2176 + row * 68 + col)) << 2;
                CP16(smb + so, Kb + go);
                CP16(smb + 4352 * 4 + so, Vb + go);
            }
            CPC();
            asm volatile("cp.async.wait_group 1;");
        } else {
            asm volatile("cp.async.wait_group 0;");
        }
        __syncthreads();

        const float* kr = SM + buf * 2176 + sl * 68 + part * 8;
        float u = 0.f, tt = 0.f;
#pragma unroll
        for (int i = 0; i < 8; ++i) { float kv = kr[i]; u += kv * rAp[i]; tt += kv * rAn[i]; }
#pragma unroll
        for (int off = 1; off < 8; off <<= 1) {
            u  += __shfl_xor_sync(0xffffffffu, u,  off);
            tt += __shfl_xor_sync(0xffffffffu, tt, off);
        }
        float l[8], mx = -1e30f;
#pragma unroll
        for (int j = 0; j < 8; ++j) { l[j] = u * ra[j] + tt * rc[j]; mx = fmaxf(mx, l[j]); }
#pragma unroll
        for (int off = 1; off < 8; off <<= 1)
            mx = fmaxf(mx, __shfl_xor_sync(0xffffffffu, mx, off));
        float sum = 0.f;
#pragma unroll
        for (int j = 0; j < 8; ++j) { l[j] = __expf(l[j] - mx); sum += l[j]; }
#pragma unroll
        for (int off = 1; off < 8; off <<= 1)
            sum += __shfl_xor_sync(0xffffffffu, sum, off);
        float inv = __fdividef(1.f, sum);
        *(float4*)&sP[sl * 68 + part * 8]     = make_float4(l[0] * inv, l[1] * inv, l[2] * inv, l[3] * inv);
        *(float4*)&sP[sl * 68 + part * 8 + 4] = make_float4(l[4] * inv, l[5] * inv, l[6] * inv, l[7] * inv);
        __syncthreads();

        const float* vb = SM + 4352 + buf * 2176;
#pragma unroll
        for (int s8 = 0; s8 < 8; ++s8) {
            int sq = quarter * 8 + s8;
            float4 v0 = *(const float4*)&vb[sq * 68 + eg * 8];
            float4 v1 = *(const float4*)&vb[sq * 68 + eg * 8 + 4];
            ulonglong2 pA = *(const ulonglong2*)&sP[sq * 68 + gg * 8];
            ulonglong2 pB = *(const ulonglong2*)&sP[sq * 68 + gg * 8 + 4];
            float ve[8] = {v0.x, v0.y, v0.z, v0.w, v1.x, v1.y, v1.z, v1.w};
#pragma unroll
            for (int e = 0; e < 8; ++e) {
                u64 vv = pack2(ve[e], ve[e]);
                fma2(acc[e * 4 + 0], vv, pA.x);
                fma2(acc[e * 4 + 1], vv, pA.y);
                fma2(acc[e * 4 + 2], vv, pB.x);
                fma2(acc[e * 4 + 3], vv, pB.y);
            }
        }
        __syncthreads();
    }

    u64* sred = (u64*)SM;
    if (tid >= 128) {
        int j = tid - 128;
#pragma unroll
        for (int i = 0; i < 32; ++i) sred[j * 32 + i] = acc[i];
    }
    __syncthreads();
    if (tid < 128) {
#pragma unroll
        for (int i = 0; i < 32; ++i) {
            float2 a = unpack2(acc[i]), c = unpack2(sred[tid * 32 + i]);
            acc[i] = pack2(a.x + c.x, a.y + c.y);
        }
    }
    __syncthreads();
    if (tid >= 64 && tid < 128) {
#pragma unroll
        for (int i = 0; i < 32; ++i) sred[(tid - 64) * 32 + i] = acc[i];
    }
    __syncthreads();
    if (tid < 64) {
#pragma unroll
        for (int i = 0; i < 32; ++i) {
            float2 a = unpack2(acc[i]), c = unpack2(sred[tid * 32 + i]);
            acc[i] = pack2(a.x + c.x, a.y + c.y);
        }
#pragma unroll
        for (int e = 0; e < 8; ++e) {
            long ob = ((long)(b * 64 + eg * 8 + e) * 8 + h) * 64 + gg * 8;
            float2 p0 = unpack2(acc[e * 4 + 0]), p1 = unpack2(acc[e * 4 + 1]);
            float2 p2 = unpack2(acc[e * 4 + 2]), p3 = unpack2(acc[e * 4 + 3]);
            *(float4*)&out[ob]     = make_float4(p0.x, p0.y, p1.x, p1.y);
            *(float4*)&out[ob + 4] = make_float4(p2.x, p2.y, p3.x, p3.y);
        }
    }
}

extern "C" void kernel_launch(void* const* d_in, const int* in_sizes, int n_in,
                              void* d_out, int out_size) {
    const float* q  = (const float*)d_in[0];
    const float* k  = (const float*)d_in[1];
    const float* v  = (const float*)d_in[2];
    const float* x  = (const float*)d_in[3];
    const float* mw = (const float*)d_in[4];
    const float* mb = (const float*)d_in[5];
    const float* sW = (const float*)d_in[6];
    (void)in_sizes; (void)n_in; (void)out_size;
    float* out = (float*)d_out;

    k1_mlp<<<512, 256>>>(x, mw, mb);
    k2_A<<<dim3(4, NH, NB), 256>>>(q);
    k3_attn<<<dim3(NH, NB), 256>>>(k, v, sW, out);
}